// round 2
// baseline (speedup 1.0000x reference)
#include <cuda_runtime.h>
#include <math.h>

#define D     128
#define ROWS  32
#define NTHR  128
#define MAXN  51200   // >= N=50000, headroom

// Scatter-add scratch: agg[N][D]. __device__ global (no cudaMalloc allowed).
__device__ float g_agg[(size_t)MAXN * D];

__device__ __forceinline__ float gelu_exact(float v) {
    // matches jax.nn.gelu(approximate=False) / torch nn.GELU default
    return 0.5f * v * (1.0f + erff(v * 0.70710678118654752f));
}

// ---------------------------------------------------------------------------
// Edge pipeline: A = x[src] + edge_attr ; H = GELU(A@W1 + b1) ; M = H@W2 + b2
// then atomicAdd M into g_agg[dst].
// Block: 32 edge-rows, 128 threads. Thread j computes output column j for all
// 32 rows (acc[32] in registers). A/H live in smem, read as broadcast float4.
// ---------------------------------------------------------------------------
__global__ void __launch_bounds__(NTHR) edge_mlp_kernel(
    const float* __restrict__ x,
    const int* __restrict__ src,
    const int* __restrict__ dst,
    const float* __restrict__ ea,
    const float* __restrict__ W1, const float* __restrict__ b1,
    const float* __restrict__ W2, const float* __restrict__ b2,
    int E)
{
    __shared__ float A[ROWS][D + 4];
    __shared__ float H[ROWS][D + 4];

    const int e0  = blockIdx.x * ROWS;
    const int tid = threadIdx.x;

    // ---- stage A = x[src] + edge_attr (zero-pad OOB rows) ----
    #pragma unroll
    for (int it = 0; it < (ROWS * D) / NTHR; ++it) {
        int idx = it * NTHR + tid;
        int r = idx >> 7;           // idx / 128
        int c = idx & (D - 1);
        int e = e0 + r;
        float v = 0.f;
        if (e < E) {
            int s = src[e];
            v = x[(size_t)s * D + c] + ea[(size_t)e * D + c];
        }
        A[r][c] = v;
    }
    __syncthreads();

    const int j = tid;   // output column owned by this thread
    float acc[ROWS];

    // ---- GEMM1 + bias + GELU -> H ----
    {
        float bj = __ldg(&b1[j]);
        #pragma unroll
        for (int r = 0; r < ROWS; ++r) acc[r] = bj;
        for (int k4 = 0; k4 < D / 4; ++k4) {
            float w0 = __ldg(&W1[(4 * k4 + 0) * D + j]);
            float w1 = __ldg(&W1[(4 * k4 + 1) * D + j]);
            float w2 = __ldg(&W1[(4 * k4 + 2) * D + j]);
            float w3 = __ldg(&W1[(4 * k4 + 3) * D + j]);
            #pragma unroll
            for (int r = 0; r < ROWS; ++r) {
                float4 a = *(const float4*)&A[r][4 * k4];
                acc[r] = fmaf(a.x, w0, acc[r]);
                acc[r] = fmaf(a.y, w1, acc[r]);
                acc[r] = fmaf(a.z, w2, acc[r]);
                acc[r] = fmaf(a.w, w3, acc[r]);
            }
        }
        #pragma unroll
        for (int r = 0; r < ROWS; ++r) H[r][j] = gelu_exact(acc[r]);
    }
    __syncthreads();

    // ---- GEMM2 + bias -> scatter-add ----
    {
        float bj = __ldg(&b2[j]);
        #pragma unroll
        for (int r = 0; r < ROWS; ++r) acc[r] = bj;
        for (int k4 = 0; k4 < D / 4; ++k4) {
            float w0 = __ldg(&W2[(4 * k4 + 0) * D + j]);
            float w1 = __ldg(&W2[(4 * k4 + 1) * D + j]);
            float w2 = __ldg(&W2[(4 * k4 + 2) * D + j]);
            float w3 = __ldg(&W2[(4 * k4 + 3) * D + j]);
            #pragma unroll
            for (int r = 0; r < ROWS; ++r) {
                float4 h = *(const float4*)&H[r][4 * k4];
                acc[r] = fmaf(h.x, w0, acc[r]);
                acc[r] = fmaf(h.y, w1, acc[r]);
                acc[r] = fmaf(h.z, w2, acc[r]);
                acc[r] = fmaf(h.w, w3, acc[r]);
            }
        }
        #pragma unroll
        for (int r = 0; r < ROWS; ++r) {
            int e = e0 + r;
            if (e < E) {
                int dn = dst[e];
                atomicAdd(&g_agg[(size_t)dn * D + j], acc[r]);
            }
        }
    }
}

// ---------------------------------------------------------------------------
// Node pipeline: A = (1+eps)*x + agg ; out = (GELU(A@Wu1+bu1))@Wu2 + bu2
// ---------------------------------------------------------------------------
__global__ void __launch_bounds__(NTHR) node_mlp_kernel(
    const float* __restrict__ x,
    const float* __restrict__ eps,
    const float* __restrict__ W1, const float* __restrict__ b1,
    const float* __restrict__ W2, const float* __restrict__ b2,
    float* __restrict__ out,
    int N)
{
    __shared__ float A[ROWS][D + 4];
    __shared__ float H[ROWS][D + 4];

    const int n0  = blockIdx.x * ROWS;
    const int tid = threadIdx.x;
    const float oe = 1.0f + eps[0];

    #pragma unroll
    for (int it = 0; it < (ROWS * D) / NTHR; ++it) {
        int idx = it * NTHR + tid;
        int r = idx >> 7;
        int c = idx & (D - 1);
        int n = n0 + r;
        float v = 0.f;
        if (n < N) {
            size_t off = (size_t)n * D + c;
            v = oe * x[off] + g_agg[off];
        }
        A[r][c] = v;
    }
    __syncthreads();

    const int j = tid;
    float acc[ROWS];

    {
        float bj = __ldg(&b1[j]);
        #pragma unroll
        for (int r = 0; r < ROWS; ++r) acc[r] = bj;
        for (int k4 = 0; k4 < D / 4; ++k4) {
            float w0 = __ldg(&W1[(4 * k4 + 0) * D + j]);
            float w1 = __ldg(&W1[(4 * k4 + 1) * D + j]);
            float w2 = __ldg(&W1[(4 * k4 + 2) * D + j]);
            float w3 = __ldg(&W1[(4 * k4 + 3) * D + j]);
            #pragma unroll
            for (int r = 0; r < ROWS; ++r) {
                float4 a = *(const float4*)&A[r][4 * k4];
                acc[r] = fmaf(a.x, w0, acc[r]);
                acc[r] = fmaf(a.y, w1, acc[r]);
                acc[r] = fmaf(a.z, w2, acc[r]);
                acc[r] = fmaf(a.w, w3, acc[r]);
            }
        }
        #pragma unroll
        for (int r = 0; r < ROWS; ++r) H[r][j] = gelu_exact(acc[r]);
    }
    __syncthreads();

    {
        float bj = __ldg(&b2[j]);
        #pragma unroll
        for (int r = 0; r < ROWS; ++r) acc[r] = bj;
        for (int k4 = 0; k4 < D / 4; ++k4) {
            float w0 = __ldg(&W2[(4 * k4 + 0) * D + j]);
            float w1 = __ldg(&W2[(4 * k4 + 1) * D + j]);
            float w2 = __ldg(&W2[(4 * k4 + 2) * D + j]);
            float w3 = __ldg(&W2[(4 * k4 + 3) * D + j]);
            #pragma unroll
            for (int r = 0; r < ROWS; ++r) {
                float4 h = *(const float4*)&H[r][4 * k4];
                acc[r] = fmaf(h.x, w0, acc[r]);
                acc[r] = fmaf(h.y, w1, acc[r]);
                acc[r] = fmaf(h.z, w2, acc[r]);
                acc[r] = fmaf(h.w, w3, acc[r]);
            }
        }
        #pragma unroll
        for (int r = 0; r < ROWS; ++r) {
            int n = n0 + r;
            if (n < N) out[(size_t)n * D + j] = acc[r];
        }
    }
}

// ---------------------------------------------------------------------------
// Inputs (metadata order): x, edge_index(int32 [2,E] — harness narrows int64),
// edge_attr, We1, be1, We2, be2, Wu1, bu1, Wu2, bu2, eps
// ---------------------------------------------------------------------------
extern "C" void kernel_launch(void* const* d_in, const int* in_sizes, int n_in,
                              void* d_out, int out_size)
{
    const float* x   = (const float*)d_in[0];
    const int*   ei  = (const int*)d_in[1];
    const float* ea  = (const float*)d_in[2];
    const float* We1 = (const float*)d_in[3];
    const float* be1 = (const float*)d_in[4];
    const float* We2 = (const float*)d_in[5];
    const float* be2 = (const float*)d_in[6];
    const float* Wu1 = (const float*)d_in[7];
    const float* bu1 = (const float*)d_in[8];
    const float* Wu2 = (const float*)d_in[9];
    const float* bu2 = (const float*)d_in[10];
    const float* eps = (const float*)d_in[11];
    float*       out = (float*)d_out;

    const int N = in_sizes[0] / D;
    const int E = in_sizes[1] / 2;

    void* aggp = nullptr;
    cudaGetSymbolAddress(&aggp, g_agg);
    cudaMemsetAsync(aggp, 0, (size_t)N * D * sizeof(float), 0);

    const int* src = ei;
    const int* dst = ei + E;

    int eblocks = (E + ROWS - 1) / ROWS;
    edge_mlp_kernel<<<eblocks, NTHR>>>(x, src, dst, ea, We1, be1, We2, be2, E);

    int nblocks = (N + ROWS - 1) / ROWS;
    node_mlp_kernel<<<nblocks, NTHR>>>(x, eps, Wu1, bu1, Wu2, bu2, out, N);
}

// round 4
// speedup vs baseline: 2.5790x; 2.5790x over previous
#include <cuda_runtime.h>
#include <math.h>
#include <stdint.h>

#define D      128
#define BROWS  128
#define NTHR   256
#define MAXN   51200
#define AST    132          // A smem row stride in floats (conflict-free frag loads)

// ---------------------------------------------------------------------------
// Static device scratch (no cudaMalloc allowed)
// ---------------------------------------------------------------------------
__device__ float    g_agg[(size_t)MAXN * D];     // scatter-add target
__device__ uint32_t g_Bfrag[4][16384];           // tf32 W images in mma-fragment order
// 0 = We1, 1 = We2, 2 = Wu1, 3 = Wu2

__device__ __forceinline__ uint32_t f2tf(float f) {
    uint32_t r;
    asm("cvt.rna.tf32.f32 %0, %1;" : "=r"(r) : "f"(f));
    return r;
}

__device__ __forceinline__ float gelu_exact(float v) {
    return 0.5f * v * (1.0f + erff(v * 0.70710678118654752f));
}

__device__ __forceinline__ void mma_tf32(float* c,
                                         uint32_t a0, uint32_t a1, uint32_t a2, uint32_t a3,
                                         uint32_t b0, uint32_t b1) {
    asm volatile(
        "mma.sync.aligned.m16n8k8.row.col.f32.tf32.tf32.f32 "
        "{%0,%1,%2,%3}, {%4,%5,%6,%7}, {%8,%9}, {%0,%1,%2,%3};"
        : "+f"(c[0]), "+f"(c[1]), "+f"(c[2]), "+f"(c[3])
        : "r"(a0), "r"(a1), "r"(a2), "r"(a3), "r"(b0), "r"(b1));
}

__device__ __forceinline__ void red_add_v4(float* p, float4 v) {
    asm volatile("red.global.add.v4.f32 [%0], {%1,%2,%3,%4};"
                 :: "l"(p), "f"(v.x), "f"(v.y), "f"(v.z), "f"(v.w) : "memory");
}

// ---------------------------------------------------------------------------
// Weight prep: W[k][n] -> tf32 bits in m16n8k8 B-fragment order.
// Fragment addressing: idx = (catom*16 + kstep)*64 + lane*2 + slot
//   catom = n>>3, kstep = k>>3, lane = ((n&7)<<2)|(k&3), slot = (k>>2)&1
// ---------------------------------------------------------------------------
__global__ void prep_weights(const float* __restrict__ We1, const float* __restrict__ We2,
                             const float* __restrict__ Wu1, const float* __restrict__ Wu2)
{
    int id = blockIdx.x * blockDim.x + threadIdx.x;
    if (id >= 4 * 16384) return;
    int m = id >> 14, r = id & 16383, k = r >> 7, n = r & 127;
    const float* W = (m == 0) ? We1 : (m == 1) ? We2 : (m == 2) ? Wu1 : Wu2;
    float v = W[k * D + n];
    int c = n >> 3, s = k >> 3, lane = ((n & 7) << 2) | (k & 3), slot = (k >> 2) & 1;
    g_Bfrag[m][(c * 16 + s) * 64 + lane * 2 + slot] = f2tf(v);
}

// ---------------------------------------------------------------------------
// One 128x128x128 GEMM on the staged A tile (tf32 bits in As) with fragment-
// ordered B in smem. Warp computes 32 rows x 64 cols.
// ---------------------------------------------------------------------------
__device__ __forceinline__ void do_gemm(const float* __restrict__ Abase,
                                        const uint32_t* __restrict__ Bw,
                                        float acc[2][8][4])
{
    #pragma unroll
    for (int ma = 0; ma < 2; ++ma)
        #pragma unroll
        for (int ca = 0; ca < 8; ++ca)
            #pragma unroll
            for (int q = 0; q < 4; ++q) acc[ma][ca][q] = 0.f;

    #pragma unroll
    for (int s = 0; s < 16; ++s) {
        uint32_t a[2][4];
        #pragma unroll
        for (int ma = 0; ma < 2; ++ma) {
            const float* q = Abase + ma * (16 * AST) + s * 8;
            a[ma][0] = __float_as_uint(q[0]);
            a[ma][1] = __float_as_uint(q[8 * AST]);
            a[ma][2] = __float_as_uint(q[4]);
            a[ma][3] = __float_as_uint(q[8 * AST + 4]);
        }
        const uint2* bp = (const uint2*)(Bw + s * 64);
        #pragma unroll
        for (int ca = 0; ca < 8; ++ca) {
            uint2 b = bp[ca * 512];       // catom stride = 1024 uints = 512 uint2
            mma_tf32(acc[0][ca], a[0][0], a[0][1], a[0][2], a[0][3], b.x, b.y);
            mma_tf32(acc[1][ca], a[1][0], a[1][1], a[1][2], a[1][3], b.x, b.y);
        }
    }
}

// ---------------------------------------------------------------------------
// Fused 2-layer MLP on a 128-row tile.
// EDGE: A = x[src]+ea -> MLP -> red.v4 scatter into g_agg[dst]
// NODE: A = (1+eps)*x + g_agg -> MLP -> out
// ---------------------------------------------------------------------------
template <bool EDGE>
__global__ void __launch_bounds__(NTHR, 1) fused_mlp_mma(
    const float* __restrict__ x,
    const int*   __restrict__ src,
    const int*   __restrict__ dst,
    const float* __restrict__ ea,
    const float* __restrict__ b1,
    const float* __restrict__ b2,
    const float* __restrict__ eps,
    float*       __restrict__ out,
    int count)
{
    extern __shared__ float smem[];
    float*    As = smem;                               // [128][AST] tf32 bits / f32
    uint32_t* Bs = (uint32_t*)(smem + BROWS * AST);    // B1 frag (16384) + B2 frag (16384)

    const int tid  = threadIdx.x;
    const int lane = tid & 31, wid = tid >> 5;
    const int wm = wid & 3, wn = wid >> 2;             // 4 row-groups x 2 col-groups
    const int g = lane >> 2, t = lane & 3;
    const int r0 = blockIdx.x * BROWS;
    const int imgbase = EDGE ? 0 : 2;

    // ---- copy both B images (128KB) ----
    {
        const uint4* gsrc = (const uint4*)(&g_Bfrag[imgbase][0]);
        uint4* s4 = (uint4*)Bs;
        #pragma unroll 8
        for (int i = tid; i < 8192; i += NTHR) s4[i] = gsrc[i];
    }

    // ---- stage A (tf32 bits) : each thread handles one row-half ----
    {
        int r = tid >> 1;
        int half = (tid & 1) * 64;
        int row = r0 + r;
        float* drow = As + r * AST + half;
        if (row < count) {
            const float4* xr;
            const float4* er;
            float oe = 0.f;
            if (EDGE) {
                int sidx = src[row];
                xr = (const float4*)(x + (size_t)sidx * D + half);
                er = (const float4*)(ea + (size_t)row * D + half);
            } else {
                oe = 1.0f + eps[0];
                xr = (const float4*)(x + (size_t)row * D + half);
                er = (const float4*)(g_agg + (size_t)row * D + half);
            }
            #pragma unroll
            for (int i = 0; i < 16; ++i) {
                float4 a = xr[i], b = er[i];
                float f0, f1, f2, f3;
                if (EDGE) { f0 = a.x + b.x; f1 = a.y + b.y; f2 = a.z + b.z; f3 = a.w + b.w; }
                else { f0 = fmaf(oe, a.x, b.x); f1 = fmaf(oe, a.y, b.y);
                       f2 = fmaf(oe, a.z, b.z); f3 = fmaf(oe, a.w, b.w); }
                uint4 u = make_uint4(f2tf(f0), f2tf(f1), f2tf(f2), f2tf(f3));
                *(uint4*)(drow + i * 4) = u;
            }
        } else {
            #pragma unroll
            for (int i = 0; i < 16; ++i)
                *(uint4*)(drow + i * 4) = make_uint4(0u, 0u, 0u, 0u);
        }
    }
    __syncthreads();

    const float* Abase = As + (wm * 32 + g) * AST + t;
    const uint32_t* Bw1 = Bs + wn * 8192 + lane * 2;           // wn*8 catoms * 1024
    const uint32_t* Bw2 = Bs + 16384 + wn * 8192 + lane * 2;

    float acc[2][8][4];

    // ---- GEMM1 ----
    do_gemm(Abase, Bw1, acc);
    __syncthreads();   // all warps done reading A before H overwrite

    // ---- epilogue1: H = GELU(C + b1) -> As (tf32 bits) ----
    #pragma unroll
    for (int ca = 0; ca < 8; ++ca) {
        int col = wn * 64 + ca * 8 + 2 * t;
        float bb0 = __ldg(&b1[col]), bb1 = __ldg(&b1[col + 1]);
        #pragma unroll
        for (int ma = 0; ma < 2; ++ma) {
            int row = wm * 32 + ma * 16 + g;
            float h0 = gelu_exact(acc[ma][ca][0] + bb0);
            float h1 = gelu_exact(acc[ma][ca][1] + bb1);
            float h2 = gelu_exact(acc[ma][ca][2] + bb0);
            float h3 = gelu_exact(acc[ma][ca][3] + bb1);
            uint2 u0 = make_uint2(f2tf(h0), f2tf(h1));
            uint2 u1 = make_uint2(f2tf(h2), f2tf(h3));
            *(uint2*)(As + row * AST + col) = u0;
            *(uint2*)(As + (row + 8) * AST + col) = u1;
        }
    }
    __syncthreads();

    // ---- GEMM2 ----
    do_gemm(Abase, Bw2, acc);
    __syncthreads();   // all warps done reading H before C2 overwrite

    // ---- epilogue2: raw C2 -> As (fp32) ----
    #pragma unroll
    for (int ca = 0; ca < 8; ++ca) {
        int col = wn * 64 + ca * 8 + 2 * t;
        #pragma unroll
        for (int ma = 0; ma < 2; ++ma) {
            int row = wm * 32 + ma * 16 + g;
            *(float2*)(As + row * AST + col)       = make_float2(acc[ma][ca][0], acc[ma][ca][1]);
            *(float2*)(As + (row + 8) * AST + col) = make_float2(acc[ma][ca][2], acc[ma][ca][3]);
        }
    }
    __syncthreads();

    // ---- output: coalesced + bias; edge -> red.v4 scatter, node -> store ----
    {
        int c4 = (tid & 31) * 4;
        float4 bias = *(const float4*)&b2[c4];
        int rbase = (tid >> 5) * 16;
        #pragma unroll
        for (int i = 0; i < 16; ++i) {
            int r = rbase + i;
            int row = r0 + r;
            if (row < count) {
                float4 v = *(float4*)(As + r * AST + c4);
                v.x += bias.x; v.y += bias.y; v.z += bias.z; v.w += bias.w;
                if (EDGE) {
                    int dn = dst[row];
                    red_add_v4(g_agg + (size_t)dn * D + c4, v);
                } else {
                    *(float4*)(out + (size_t)row * D + c4) = v;
                }
            }
        }
    }
}

// ---------------------------------------------------------------------------
// Inputs: x, edge_index(int32 [2,E]), edge_attr, We1, be1, We2, be2,
//         Wu1, bu1, Wu2, bu2, eps
// ---------------------------------------------------------------------------
extern "C" void kernel_launch(void* const* d_in, const int* in_sizes, int n_in,
                              void* d_out, int out_size)
{
    const float* x   = (const float*)d_in[0];
    const int*   ei  = (const int*)d_in[1];
    const float* ea  = (const float*)d_in[2];
    const float* We1 = (const float*)d_in[3];
    const float* be1 = (const float*)d_in[4];
    const float* We2 = (const float*)d_in[5];
    const float* be2 = (const float*)d_in[6];
    const float* Wu1 = (const float*)d_in[7];
    const float* bu1 = (const float*)d_in[8];
    const float* Wu2 = (const float*)d_in[9];
    const float* bu2 = (const float*)d_in[10];
    const float* eps = (const float*)d_in[11];
    float*       out = (float*)d_out;

    const int N = in_sizes[0] / D;
    const int E = in_sizes[1] / 2;
    const int* src = ei;
    const int* dst = ei + E;

    const int SMEM_BYTES = (BROWS * AST + 2 * 16384) * 4;   // 198656
    cudaFuncSetAttribute(fused_mlp_mma<true>,  cudaFuncAttributeMaxDynamicSharedMemorySize, SMEM_BYTES);
    cudaFuncSetAttribute(fused_mlp_mma<false>, cudaFuncAttributeMaxDynamicSharedMemorySize, SMEM_BYTES);

    prep_weights<<<256, 256>>>(We1, We2, Wu1, Wu2);

    void* aggp = nullptr;
    cudaGetSymbolAddress(&aggp, g_agg);
    cudaMemsetAsync(aggp, 0, (size_t)N * D * sizeof(float), 0);

    int eblocks = (E + BROWS - 1) / BROWS;
    fused_mlp_mma<true><<<eblocks, NTHR, SMEM_BYTES>>>(x, src, dst, ea, be1, be2, eps, out, E);

    int nblocks = (N + BROWS - 1) / BROWS;
    fused_mlp_mma<false><<<nblocks, NTHR, SMEM_BYTES>>>(x, src, dst, ea, bu1, bu2, eps, out, N);
}